// round 1
// baseline (speedup 1.0000x reference)
#include <cuda_runtime.h>
#include <cuda_bf16.h>
#include <math.h>

// Problem constants
#define B_  4
#define C_  2
#define H_  2048
#define W_  128
#define HP  2050   // H + 2*PAD
#define WP  130    // W + 2*PAD
#define KS_ 3
#define N_  9      // KS*KS

// Scratch (device globals; no allocations allowed)
__device__ float  g_fm[B_ * C_ * 128 * 128];          // fm after sigmoid, [b][c][k][w]
__device__ float4 g_xp4[B_ * HP * WP];                // padded NHWC x: (sar0,sar1,fs0,fs1)

// ---------------------------------------------------------------------------
// Kernel A: block-mean (16x1) + 1x1 channel mix + sigmoid -> g_fm
// one thread per (b, i, j), 65536 threads
// ---------------------------------------------------------------------------
__global__ void kA_avg_fm(const float* __restrict__ rgb, const float* __restrict__ wfm) {
    int tid = blockIdx.x * blockDim.x + threadIdx.x;
    if (tid >= B_ * 128 * 128) return;
    int j = tid & 127;
    int i = (tid >> 7) & 127;
    int b = tid >> 14;

    const float* r0 = rgb + ((size_t)(b * 2 + 0) * H_ + i * 16) * W_ + j;
    const float* r1 = rgb + ((size_t)(b * 2 + 1) * H_ + i * 16) * W_ + j;
    float a0 = 0.f, a1 = 0.f;
#pragma unroll
    for (int r = 0; r < 16; r++) {
        a0 += __ldg(&r0[r * W_]);
        a1 += __ldg(&r1[r * W_]);
    }
    a0 *= (1.f / 16.f);
    a1 *= (1.f / 16.f);

    float w00 = __ldg(&wfm[0]), w01 = __ldg(&wfm[1]);
    float w10 = __ldg(&wfm[2]), w11 = __ldg(&wfm[3]);
    float z0 = w00 * a0 + w01 * a1;
    float z1 = w10 * a0 + w11 * a1;
    g_fm[((b * 2 + 0) * 128 + i) * 128 + j] = 1.f / (1.f + expf(-z0));
    g_fm[((b * 2 + 1) * 128 + i) * 128 + j] = 1.f / (1.f + expf(-z1));
}

// ---------------------------------------------------------------------------
// Kernel Z: zero the 1-pixel padding border of g_xp4
// one thread per (b, y)
// ---------------------------------------------------------------------------
__global__ void kZ_zero_border() {
    int tid = blockIdx.x * blockDim.x + threadIdx.x;
    if (tid >= B_ * HP) return;
    int b = tid / HP;
    int y = tid % HP;
    float4* row = g_xp4 + ((size_t)b * HP + y) * WP;
    float4 z = make_float4(0.f, 0.f, 0.f, 0.f);
    if (y == 0 || y == HP - 1) {
        for (int x = 0; x < WP; x++) row[x] = z;
    } else {
        row[0] = z;
        row[WP - 1] = z;
    }
}

// ---------------------------------------------------------------------------
// Kernel B: mat = rgb @ fm + rgb (per b,c), fs = w_fs channel mix,
//           pack (sar0,sar1,fs0,fs1) into padded NHWC g_xp4 interior.
// grid (32, 4) = (row tiles of 64, batch), block (128, 2).
// smem: fm[b] both channels (128 KB) + rgb tile [2][64][128] (64 KB) = 192 KB
// Each thread: column tx, rows ty*32..ty*32+31, both channels (64 accumulators)
// ---------------------------------------------------------------------------
#define KB_ROWS 64
__global__ void kB_mat_fs_pack(const float* __restrict__ rgb,
                               const float* __restrict__ sar,
                               const float* __restrict__ wfs) {
    extern __shared__ float sm[];
    float* s_fm  = sm;            // 2*128*128 = 32768 floats
    float* s_rgb = sm + 32768;    // 2*64*128  = 16384 floats

    int tx = threadIdx.x;         // 0..127 (output column w)
    int ty = threadIdx.y;         // 0..1
    int tid = ty * 128 + tx;
    int b  = blockIdx.y;
    int h0 = blockIdx.x * KB_ROWS;

    const float* fmb = g_fm + (size_t)b * 32768;
    for (int i = tid; i < 32768; i += 256) s_fm[i] = fmb[i];

    const float* rgbb = rgb + (size_t)b * 2 * H_ * W_;
    for (int i = tid; i < 2 * KB_ROWS * 128; i += 256) {
        int c  = i >> 13;            // / 8192
        int rk = i & 8191;
        int r  = rk >> 7;
        int k  = rk & 127;
        s_rgb[i] = rgbb[(size_t)c * H_ * W_ + (size_t)(h0 + r) * W_ + k];
    }
    __syncthreads();

    float acc0[32], acc1[32];
#pragma unroll
    for (int r = 0; r < 32; r++) { acc0[r] = 0.f; acc1[r] = 0.f; }

    const float* sr0 = s_rgb + (ty * 32) * 128;          // channel 0 rows
    const float* sr1 = s_rgb + 8192 + (ty * 32) * 128;   // channel 1 rows

#pragma unroll 4
    for (int k = 0; k < 128; k++) {
        float f0 = s_fm[k * 128 + tx];
        float f1 = s_fm[16384 + k * 128 + tx];
#pragma unroll
        for (int r = 0; r < 32; r++) {
            acc0[r] = fmaf(sr0[r * 128 + k], f0, acc0[r]);
            acc1[r] = fmaf(sr1[r * 128 + k], f1, acc1[r]);
        }
    }

    float wfs00 = __ldg(&wfs[0]), wfs01 = __ldg(&wfs[1]);
    float wfs10 = __ldg(&wfs[2]), wfs11 = __ldg(&wfs[3]);
    const float* sarb = sar + (size_t)b * 2 * H_ * W_;
    float4* xb = g_xp4 + (size_t)b * HP * WP;

#pragma unroll
    for (int r = 0; r < 32; r++) {
        int row = ty * 32 + r;
        int h = h0 + row;
        float mat0 = acc0[r] + sr0[r * 128 + tx];
        float mat1 = acc1[r] + sr1[r * 128 + tx];
        float fs0 = wfs00 * mat0 + wfs01 * mat1;
        float fs1 = wfs10 * mat0 + wfs11 * mat1;
        float s0 = __ldg(&sarb[(size_t)h * W_ + tx]);
        float s1 = __ldg(&sarb[(size_t)H_ * W_ + (size_t)h * W_ + tx]);
        xb[(size_t)(h + 1) * WP + (tx + 1)] = make_float4(s0, s1, fs0, fs1);
    }
}

// ---------------------------------------------------------------------------
// Kernel C: offset conv (3x3, 4ch -> 18ch) + 9-point bilinear deform sampling
//           + final 2-ch output dot.
// grid (2048, 4) = (h, b), block 128 (= one W row). smem: 3 padded rows NHWC.
// ---------------------------------------------------------------------------
__global__ void kC_deform(const float* __restrict__ wp,
                          const float* __restrict__ bp,
                          const float* __restrict__ wdc,
                          float* __restrict__ out) {
    __shared__ float4 srow[3][WP];
    __shared__ float  swp[648];
    __shared__ float  sbp[18];
    __shared__ float  swdc[72];

    int w = threadIdx.x;   // 0..127
    int h = blockIdx.x;    // 0..2047
    int b = blockIdx.y;    // 0..3

    const float4* base = g_xp4 + (size_t)b * HP * WP;

    for (int i = threadIdx.x; i < 3 * WP; i += 128) {
        int ry = i / WP, rx = i % WP;
        srow[ry][rx] = base[(size_t)(h + ry) * WP + rx];
    }
    for (int i = threadIdx.x; i < 648; i += 128) swp[i] = wp[i];
    if (threadIdx.x < 18) sbp[threadIdx.x] = bp[threadIdx.x];
    if (threadIdx.x < 72) swdc[threadIdx.x] = wdc[threadIdx.x];
    __syncthreads();

    // offset conv: off[j] = b_p[j] + sum_{c,tap} w_p[j][c][tap] * xp[c][h+ky][w+kx]
    float off[18];
#pragma unroll
    for (int j = 0; j < 18; j++) off[j] = sbp[j];

#pragma unroll
    for (int ky = 0; ky < 3; ky++) {
#pragma unroll
        for (int kx = 0; kx < 3; kx++) {
            float4 v = srow[ky][w + kx];
            int tap = ky * 3 + kx;
#pragma unroll
            for (int j = 0; j < 18; j++) {
                const float* wj = &swp[j * 36 + tap];   // c stride = 9
                off[j] += v.x * wj[0] + v.y * wj[9] + v.z * wj[18] + v.w * wj[27];
            }
        }
    }

    float acc0 = 0.f, acc1 = 0.f;
    float pybase = (float)(h + 1);
    float pxbase = (float)(w + 1);

#pragma unroll
    for (int n = 0; n < 9; n++) {
        float dy = (float)(n / 3 - 1);
        float dx = (float)(n % 3 - 1);
        float py = pybase + dy + off[n];
        float px = pxbase + dx + off[9 + n];

        float fy = floorf(py), fx = floorf(px);
        float y0f = fminf(fmaxf(fy,       0.f), (float)(HP - 1));
        float y1f = fminf(fmaxf(fy + 1.f, 0.f), (float)(HP - 1));
        float x0f = fminf(fmaxf(fx,       0.f), (float)(WP - 1));
        float x1f = fminf(fmaxf(fx + 1.f, 0.f), (float)(WP - 1));
        int y0 = (int)y0f, y1 = (int)y1f, x0 = (int)x0f, x1 = (int)x1f;

        float pyc = fminf(fmaxf(py, 0.f), (float)(HP - 1));
        float pxc = fminf(fmaxf(px, 0.f), (float)(WP - 1));

        float wy0 = 1.f + (y0f - pyc);
        float wy1 = 1.f - (y1f - pyc);
        float wx0 = 1.f + (x0f - pxc);
        float wx1 = 1.f - (x1f - pxc);

        float glt = wy0 * wx0;
        float grb = wy1 * wx1;
        float glb = wy0 * wx1;
        float grt = wy1 * wx0;

        float4 vlt = __ldg(&base[(size_t)y0 * WP + x0]);
        float4 vrb = __ldg(&base[(size_t)y1 * WP + x1]);
        float4 vlb = __ldg(&base[(size_t)y0 * WP + x1]);
        float4 vrt = __ldg(&base[(size_t)y1 * WP + x0]);

        float c0 = glt * vlt.x + grb * vrb.x + glb * vlb.x + grt * vrt.x;
        float c1 = glt * vlt.y + grb * vrb.y + glb * vlb.y + grt * vrt.y;
        float c2 = glt * vlt.z + grb * vrb.z + glb * vlb.z + grt * vrt.z;
        float c3 = glt * vlt.w + grb * vrb.w + glb * vlb.w + grt * vrt.w;

        acc0 += c0 * swdc[0 * 36 + 0 * 9 + n] + c1 * swdc[0 * 36 + 1 * 9 + n]
              + c2 * swdc[0 * 36 + 2 * 9 + n] + c3 * swdc[0 * 36 + 3 * 9 + n];
        acc1 += c0 * swdc[1 * 36 + 0 * 9 + n] + c1 * swdc[1 * 36 + 1 * 9 + n]
              + c2 * swdc[1 * 36 + 2 * 9 + n] + c3 * swdc[1 * 36 + 3 * 9 + n];
    }

    out[((size_t)(b * 2 + 0) * H_ + h) * W_ + w] = acc0;
    out[((size_t)(b * 2 + 1) * H_ + h) * W_ + w] = acc1;
}

// ---------------------------------------------------------------------------
extern "C" void kernel_launch(void* const* d_in, const int* in_sizes, int n_in,
                              void* d_out, int out_size) {
    const float* rgb = (const float*)d_in[0];
    const float* sar = (const float*)d_in[1];
    const float* wfm = (const float*)d_in[2];
    const float* wfs = (const float*)d_in[3];
    const float* wp  = (const float*)d_in[4];
    const float* bp  = (const float*)d_in[5];
    const float* wdc = (const float*)d_in[6];
    float* out = (float*)d_out;

    // 192 KB dynamic smem for kernel B (idempotent; safe during capture)
    cudaFuncSetAttribute(kB_mat_fs_pack,
                         cudaFuncAttributeMaxDynamicSharedMemorySize, 196608);

    // A: avg + fm
    kA_avg_fm<<<(B_ * 128 * 128 + 255) / 256, 256>>>(rgb, wfm);
    // Z: zero padding border of xp4 (independent of A/B outputs' interior)
    kZ_zero_border<<<(B_ * HP + 255) / 256, 256>>>();
    // B: mat + fs + pack NHWC padded
    kB_mat_fs_pack<<<dim3(H_ / KB_ROWS, B_), dim3(128, 2), 196608>>>(rgb, sar, wfs);
    // C: offset conv + deformable sampling + output
    kC_deform<<<dim3(H_, B_), 128>>>(wp, bp, wdc, out);
}

// round 2
// speedup vs baseline: 1.7641x; 1.7641x over previous
#include <cuda_runtime.h>
#include <cuda_bf16.h>
#include <math.h>

#define B_  4
#define C_  2
#define H_  2048
#define W_  128
#define HP  2050
#define WP  130

typedef unsigned long long u64;

__device__ __forceinline__ u64 ffma2(u64 a, u64 b, u64 c) {
    u64 d; asm("fma.rn.f32x2 %0, %1, %2, %3;" : "=l"(d) : "l"(a), "l"(b), "l"(c)); return d;
}
__device__ __forceinline__ u64 dup2(float x) {
    u64 d; asm("mov.b64 %0, {%1, %1};" : "=l"(d) : "f"(x)); return d;
}
__device__ __forceinline__ float2 un2(u64 v) {
    float2 r; asm("mov.b64 {%0, %1}, %2;" : "=f"(r.x), "=f"(r.y) : "l"(v)); return r;
}

// Scratch
__device__ float  g_fm[B_ * C_ * 128 * 128];   // fm after sigmoid [b][c][k][w]
__device__ float4 g_xp4[B_ * HP * WP];         // padded NHWC (sar0,sar1,fs0,fs1)

// ---------------------------------------------------------------------------
// Kernel A: 16x1 block mean + 1x1 mix + sigmoid
// ---------------------------------------------------------------------------
__global__ void kA_avg_fm(const float* __restrict__ rgb, const float* __restrict__ wfm) {
    int tid = blockIdx.x * blockDim.x + threadIdx.x;
    if (tid >= B_ * 128 * 128) return;
    int j = tid & 127;
    int i = (tid >> 7) & 127;
    int b = tid >> 14;

    const float* r0 = rgb + ((size_t)(b * 2 + 0) * H_ + i * 16) * W_ + j;
    const float* r1 = rgb + ((size_t)(b * 2 + 1) * H_ + i * 16) * W_ + j;
    float a0 = 0.f, a1 = 0.f;
#pragma unroll
    for (int r = 0; r < 16; r++) {
        a0 += __ldg(&r0[r * W_]);
        a1 += __ldg(&r1[r * W_]);
    }
    a0 *= (1.f / 16.f);
    a1 *= (1.f / 16.f);

    float w00 = __ldg(&wfm[0]), w01 = __ldg(&wfm[1]);
    float w10 = __ldg(&wfm[2]), w11 = __ldg(&wfm[3]);
    float z0 = w00 * a0 + w01 * a1;
    float z1 = w10 * a0 + w11 * a1;
    g_fm[((b * 2 + 0) * 128 + i) * 128 + j] = 1.f / (1.f + expf(-z0));
    g_fm[((b * 2 + 1) * 128 + i) * 128 + j] = 1.f / (1.f + expf(-z1));
}

// ---------------------------------------------------------------------------
// Kernel Z: zero the 1-pixel border of g_xp4
// ---------------------------------------------------------------------------
__global__ void kZ_zero_border() {
    int tid = blockIdx.x * blockDim.x + threadIdx.x;
    if (tid >= B_ * HP) return;
    int b = tid / HP;
    int y = tid % HP;
    float4* row = g_xp4 + ((size_t)b * HP + y) * WP;
    float4 z = make_float4(0.f, 0.f, 0.f, 0.f);
    if (y == 0 || y == HP - 1) {
        for (int x = 0; x < WP; x++) row[x] = z;
    } else {
        row[0] = z;
        row[WP - 1] = z;
    }
}

// ---------------------------------------------------------------------------
// Kernel B: mat = rgb @ fm + rgb, fs = w_fs mix, pack padded NHWC.
// Channel-interleaved smem + f32x2: 1 FFMA2 per (row,k) covers both channels.
// block (128,4)=512 thr, 64 rows/block, 16 rows/thread. smem 192 KB.
// ---------------------------------------------------------------------------
#define KB_ROWS 64
__global__ void __launch_bounds__(512, 1)
kB_mat_fs_pack(const float* __restrict__ rgb,
               const float* __restrict__ sar,
               const float* __restrict__ wfs) {
    extern __shared__ float sm[];
    float* s_fmi  = sm;            // [k][w][ch]   2*128*128 floats
    float* s_rgbi = sm + 32768;    // [r][k][ch]   2*64*128 floats

    int tx = threadIdx.x;          // 0..127 output column
    int ty = threadIdx.y;          // 0..3
    int tid = ty * 128 + tx;
    int b  = blockIdx.y;
    int h0 = blockIdx.x * KB_ROWS;

    const float* fmb = g_fm + (size_t)b * 32768;
    for (int i = tid; i < 16384; i += 512) {
        s_fmi[i * 2 + 0] = fmb[i];           // ch0: [k][w]
        s_fmi[i * 2 + 1] = fmb[16384 + i];   // ch1
    }
    const float* rgbb = rgb + (size_t)b * 2 * H_ * W_;
    for (int i = tid; i < KB_ROWS * 128; i += 512) {
        int r = i >> 7, k = i & 127;
        s_rgbi[i * 2 + 0] = rgbb[(size_t)(h0 + r) * W_ + k];
        s_rgbi[i * 2 + 1] = rgbb[(size_t)H_ * W_ + (size_t)(h0 + r) * W_ + k];
    }
    __syncthreads();

    u64 acc[16];
#pragma unroll
    for (int r = 0; r < 16; r++) acc[r] = 0ULL;

    int rbase = ty * 16;
#pragma unroll 2
    for (int k = 0; k < 128; k++) {
        u64 fp = *(const u64*)&s_fmi[(k * 128 + tx) * 2];
#pragma unroll
        for (int r = 0; r < 16; r++) {
            u64 xp = *(const u64*)&s_rgbi[((rbase + r) * 128 + k) * 2];
            acc[r] = ffma2(xp, fp, acc[r]);
        }
    }

    float wfs00 = __ldg(&wfs[0]), wfs01 = __ldg(&wfs[1]);
    float wfs10 = __ldg(&wfs[2]), wfs11 = __ldg(&wfs[3]);
    const float* sarb = sar + (size_t)b * 2 * H_ * W_;
    float4* xb = g_xp4 + (size_t)b * HP * WP;

#pragma unroll
    for (int r = 0; r < 16; r++) {
        int row = rbase + r;
        int h = h0 + row;
        float2 m = un2(acc[r]);
        float mat0 = m.x + s_rgbi[(row * 128 + tx) * 2 + 0];
        float mat1 = m.y + s_rgbi[(row * 128 + tx) * 2 + 1];
        float fs0 = wfs00 * mat0 + wfs01 * mat1;
        float fs1 = wfs10 * mat0 + wfs11 * mat1;
        float s0 = __ldg(&sarb[(size_t)h * W_ + tx]);
        float s1 = __ldg(&sarb[(size_t)H_ * W_ + (size_t)h * W_ + tx]);
        xb[(size_t)(h + 1) * WP + (tx + 1)] = make_float4(s0, s1, fs0, fs1);
    }
}

// ---------------------------------------------------------------------------
// Kernel C: offset conv + bilinear deform sampling + output dot, f32x2 packed.
// block 128 thr processes TILE_H=8 rows; grid (256, 4).
// ---------------------------------------------------------------------------
#define TILE_H 8
__global__ void __launch_bounds__(128, 5)
kC_deform(const float* __restrict__ wp,
          const float* __restrict__ bp,
          const float* __restrict__ wdc,
          float* __restrict__ out) {
    __shared__ float4 srow[TILE_H + 2][WP];  // 20800 B
    __shared__ float  swq[648];              // wp reordered [j][tap][c]
    __shared__ float  sdc[72];               // wdc as pairs [n][c][(o0,o1)]
    __shared__ float  sbp[18];

    int w  = threadIdx.x;        // 0..127
    int h0 = blockIdx.x * TILE_H;
    int b  = blockIdx.y;

    const float4* base = g_xp4 + (size_t)b * HP * WP;

    for (int i = threadIdx.x; i < (TILE_H + 2) * WP; i += 128) {
        int ry = i / WP, rx = i % WP;
        srow[ry][rx] = base[(size_t)(h0 + ry) * WP + rx];
    }
    for (int i = threadIdx.x; i < 648; i += 128) {
        int j = i / 36, rem = i % 36, tap = rem / 4, c = rem % 4;
        swq[i] = wp[j * 36 + c * 9 + tap];
    }
    if (threadIdx.x < 72) {
        int i = threadIdx.x;
        int n = i / 8, rc = i % 8, c = rc / 2, o = rc % 2;
        sdc[i] = wdc[o * 36 + c * 9 + n];
    }
    if (threadIdx.x < 18) sbp[threadIdx.x] = bp[threadIdx.x];
    __syncthreads();

    const float pxbase = (float)(w + 1);

#pragma unroll 1
    for (int r = 0; r < TILE_H; r++) {
        // input taps as f32x2 pairs: ip[tap] = {(c0,c1),(c2,c3)}
        ulonglong2 ip[9];
#pragma unroll
        for (int ky = 0; ky < 3; ky++)
#pragma unroll
            for (int kx = 0; kx < 3; kx++)
                ip[ky * 3 + kx] = *(const ulonglong2*)&srow[r + ky][w + kx];

        // offset conv: per j, 9 broadcast LDS.128 + 18 FFMA2
        float off[18];
#pragma unroll
        for (int j = 0; j < 18; j++) {
            u64 acc = 0ULL;
            const ulonglong2* wq = (const ulonglong2*)(swq + j * 36);
#pragma unroll
            for (int tap = 0; tap < 9; tap++) {
                ulonglong2 wv = wq[tap];
                acc = ffma2(ip[tap].x, wv.x, acc);
                acc = ffma2(ip[tap].y, wv.y, acc);
            }
            float2 a = un2(acc);
            off[j] = a.x + a.y + sbp[j];
        }

        int h = h0 + r;
        float pybase = (float)(h + 1);
        u64 accp = 0ULL;   // (out0, out1)

#pragma unroll
        for (int n = 0; n < 9; n++) {
            float dy = (float)(n / 3 - 1);
            float dx = (float)(n % 3 - 1);
            float py = pybase + dy + off[n];
            float px = pxbase + dx + off[9 + n];

            float fy = floorf(py), fx = floorf(px);
            float y0f = fminf(fmaxf(fy,       0.f), (float)(HP - 1));
            float y1f = fminf(fmaxf(fy + 1.f, 0.f), (float)(HP - 1));
            float x0f = fminf(fmaxf(fx,       0.f), (float)(WP - 1));
            float x1f = fminf(fmaxf(fx + 1.f, 0.f), (float)(WP - 1));
            int y0 = (int)y0f, y1 = (int)y1f, x0 = (int)x0f, x1 = (int)x1f;

            float pyc = fminf(fmaxf(py, 0.f), (float)(HP - 1));
            float pxc = fminf(fmaxf(px, 0.f), (float)(WP - 1));

            float wy0 = 1.f + (y0f - pyc);
            float wy1 = 1.f - (y1f - pyc);
            float wx0 = 1.f + (x0f - pxc);
            float wx1 = 1.f - (x1f - pxc);

            float glt = wy0 * wx0;
            float grb = wy1 * wx1;
            float glb = wy0 * wx1;
            float grt = wy1 * wx0;

            ulonglong2 vlt = __ldg((const ulonglong2*)(base + (size_t)y0 * WP + x0));
            ulonglong2 vrb = __ldg((const ulonglong2*)(base + (size_t)y1 * WP + x1));
            ulonglong2 vlb = __ldg((const ulonglong2*)(base + (size_t)y0 * WP + x1));
            ulonglong2 vrt = __ldg((const ulonglong2*)(base + (size_t)y1 * WP + x0));

            u64 glt2 = dup2(glt), grb2 = dup2(grb), glb2 = dup2(glb), grt2 = dup2(grt);
            u64 c01 = ffma2(glt2, vlt.x, ffma2(grb2, vrb.x, ffma2(glb2, vlb.x, ffma2(grt2, vrt.x, 0ULL))));
            u64 c23 = ffma2(glt2, vlt.y, ffma2(grb2, vrb.y, ffma2(glb2, vlb.y, ffma2(grt2, vrt.y, 0ULL))));

            float2 c01f = un2(c01), c23f = un2(c23);
            const ulonglong2* sd = (const ulonglong2*)(sdc + n * 8);
            ulonglong2 w01 = sd[0], w23 = sd[1];
            accp = ffma2(dup2(c01f.x), w01.x, accp);
            accp = ffma2(dup2(c01f.y), w01.y, accp);
            accp = ffma2(dup2(c23f.x), w23.x, accp);
            accp = ffma2(dup2(c23f.y), w23.y, accp);
        }

        float2 oo = un2(accp);
        out[((size_t)(b * 2 + 0) * H_ + h) * W_ + w] = oo.x;
        out[((size_t)(b * 2 + 1) * H_ + h) * W_ + w] = oo.y;
    }
}

// ---------------------------------------------------------------------------
extern "C" void kernel_launch(void* const* d_in, const int* in_sizes, int n_in,
                              void* d_out, int out_size) {
    const float* rgb = (const float*)d_in[0];
    const float* sar = (const float*)d_in[1];
    const float* wfm = (const float*)d_in[2];
    const float* wfs = (const float*)d_in[3];
    const float* wp  = (const float*)d_in[4];
    const float* bp  = (const float*)d_in[5];
    const float* wdc = (const float*)d_in[6];
    float* out = (float*)d_out;

    cudaFuncSetAttribute(kB_mat_fs_pack,
                         cudaFuncAttributeMaxDynamicSharedMemorySize, 196608);

    kA_avg_fm<<<(B_ * 128 * 128 + 255) / 256, 256>>>(rgb, wfm);
    kZ_zero_border<<<(B_ * HP + 255) / 256, 256>>>();
    kB_mat_fs_pack<<<dim3(H_ / KB_ROWS, B_), dim3(128, 4), 196608>>>(rgb, sar, wfs);
    kC_deform<<<dim3(H_ / TILE_H, B_), 128>>>(wp, bp, wdc, out);
}

// round 3
// speedup vs baseline: 1.8979x; 1.0759x over previous
#include <cuda_runtime.h>
#include <cuda_fp16.h>
#include <math.h>

#define B_  4
#define C_  2
#define H_  2048
#define W_  128
#define HP  2050
#define WP  130

typedef unsigned long long u64;

__device__ __forceinline__ u64 ffma2(u64 a, u64 b, u64 c) {
    u64 d; asm("fma.rn.f32x2 %0, %1, %2, %3;" : "=l"(d) : "l"(a), "l"(b), "l"(c)); return d;
}
__device__ __forceinline__ u64 dup2(float x) {
    u64 d; asm("mov.b64 %0, {%1, %1};" : "=l"(d) : "f"(x)); return d;
}
__device__ __forceinline__ u64 pk2(float x, float y) {
    u64 d; asm("mov.b64 %0, {%1, %2};" : "=l"(d) : "f"(x), "f"(y)); return d;
}
__device__ __forceinline__ float2 un2(u64 v) {
    float2 r; asm("mov.b64 {%0, %1}, %2;" : "=f"(r.x), "=f"(r.y) : "l"(v)); return r;
}
// low/high half2 of a u64 (4 fp16) -> f32x2
__device__ __forceinline__ u64 cvlo(u64 p) {
    unsigned lo = (unsigned)p;
    float2 f = __half22float2(*(__half2*)&lo);
    return pk2(f.x, f.y);
}
__device__ __forceinline__ u64 cvhi(u64 p) {
    unsigned hi = (unsigned)(p >> 32);
    float2 f = __half22float2(*(__half2*)&hi);
    return pk2(f.x, f.y);
}

// Scratch
__device__ float      g_fm[B_ * C_ * 128 * 128];  // fm after sigmoid [b][c][k][w]
__device__ float4     g_xp4[B_ * HP * WP];        // padded NHWC fp32 (sar0,sar1,fs0,fs1)
__device__ u64        g_xh [B_ * HP * WP];        // padded NHWC fp16x4
__device__ ulonglong2 g_xh2[B_ * HP * WP];        // x-duplicated: slot x = (px[x], px[x+1])

// ---------------------------------------------------------------------------
// Kernel A: 16x1 block mean + 1x1 mix + sigmoid
// ---------------------------------------------------------------------------
__global__ void kA_avg_fm(const float* __restrict__ rgb, const float* __restrict__ wfm) {
    int tid = blockIdx.x * blockDim.x + threadIdx.x;
    if (tid >= B_ * 128 * 128) return;
    int j = tid & 127;
    int i = (tid >> 7) & 127;
    int b = tid >> 14;

    const float* r0 = rgb + ((size_t)(b * 2 + 0) * H_ + i * 16) * W_ + j;
    const float* r1 = rgb + ((size_t)(b * 2 + 1) * H_ + i * 16) * W_ + j;
    float a0 = 0.f, a1 = 0.f;
#pragma unroll
    for (int r = 0; r < 16; r++) {
        a0 += __ldg(&r0[r * W_]);
        a1 += __ldg(&r1[r * W_]);
    }
    a0 *= (1.f / 16.f);
    a1 *= (1.f / 16.f);

    float w00 = __ldg(&wfm[0]), w01 = __ldg(&wfm[1]);
    float w10 = __ldg(&wfm[2]), w11 = __ldg(&wfm[3]);
    float z0 = w00 * a0 + w01 * a1;
    float z1 = w10 * a0 + w11 * a1;
    g_fm[((b * 2 + 0) * 128 + i) * 128 + j] = 1.f / (1.f + expf(-z0));
    g_fm[((b * 2 + 1) * 128 + i) * 128 + j] = 1.f / (1.f + expf(-z1));
}

// ---------------------------------------------------------------------------
// Kernel Z: zero 1-pixel borders of g_xp4 and g_xh
// ---------------------------------------------------------------------------
__global__ void kZ_zero_border() {
    int tid = blockIdx.x * blockDim.x + threadIdx.x;
    if (tid >= B_ * HP) return;
    int b = tid / HP;
    int y = tid % HP;
    size_t rb = ((size_t)b * HP + y) * WP;
    float4 z = make_float4(0.f, 0.f, 0.f, 0.f);
    if (y == 0 || y == HP - 1) {
        for (int x = 0; x < WP; x++) { g_xp4[rb + x] = z; g_xh[rb + x] = 0ULL; }
    } else {
        g_xp4[rb] = z;           g_xh[rb] = 0ULL;
        g_xp4[rb + WP - 1] = z;  g_xh[rb + WP - 1] = 0ULL;
    }
}

// ---------------------------------------------------------------------------
// Kernel B: mat = rgb @ fm + rgb, fs = w_fs mix, pack fp32 NHWC + fp16 NHWC
// ---------------------------------------------------------------------------
#define KB_ROWS 64
__global__ void __launch_bounds__(512, 1)
kB_mat_fs_pack(const float* __restrict__ rgb,
               const float* __restrict__ sar,
               const float* __restrict__ wfs) {
    extern __shared__ float sm[];
    float* s_fmi  = sm;            // [k][w][ch]
    float* s_rgbi = sm + 32768;    // [r][k][ch]

    int tx = threadIdx.x;
    int ty = threadIdx.y;
    int tid = ty * 128 + tx;
    int b  = blockIdx.y;
    int h0 = blockIdx.x * KB_ROWS;

    const float* fmb = g_fm + (size_t)b * 32768;
    for (int i = tid; i < 16384; i += 512) {
        s_fmi[i * 2 + 0] = fmb[i];
        s_fmi[i * 2 + 1] = fmb[16384 + i];
    }
    const float* rgbb = rgb + (size_t)b * 2 * H_ * W_;
    for (int i = tid; i < KB_ROWS * 128; i += 512) {
        int r = i >> 7, k = i & 127;
        s_rgbi[i * 2 + 0] = rgbb[(size_t)(h0 + r) * W_ + k];
        s_rgbi[i * 2 + 1] = rgbb[(size_t)H_ * W_ + (size_t)(h0 + r) * W_ + k];
    }
    __syncthreads();

    u64 acc[16];
#pragma unroll
    for (int r = 0; r < 16; r++) acc[r] = 0ULL;

    int rbase = ty * 16;
#pragma unroll 2
    for (int k = 0; k < 128; k++) {
        u64 fp = *(const u64*)&s_fmi[(k * 128 + tx) * 2];
#pragma unroll
        for (int r = 0; r < 16; r++) {
            u64 xp = *(const u64*)&s_rgbi[((rbase + r) * 128 + k) * 2];
            acc[r] = ffma2(xp, fp, acc[r]);
        }
    }

    float wfs00 = __ldg(&wfs[0]), wfs01 = __ldg(&wfs[1]);
    float wfs10 = __ldg(&wfs[2]), wfs11 = __ldg(&wfs[3]);
    const float* sarb = sar + (size_t)b * 2 * H_ * W_;
    float4* xb = g_xp4 + (size_t)b * HP * WP;
    u64*    hb = g_xh  + (size_t)b * HP * WP;

#pragma unroll
    for (int r = 0; r < 16; r++) {
        int row = rbase + r;
        int h = h0 + row;
        float2 m = un2(acc[r]);
        float mat0 = m.x + s_rgbi[(row * 128 + tx) * 2 + 0];
        float mat1 = m.y + s_rgbi[(row * 128 + tx) * 2 + 1];
        float fs0 = wfs00 * mat0 + wfs01 * mat1;
        float fs1 = wfs10 * mat0 + wfs11 * mat1;
        float s0 = __ldg(&sarb[(size_t)h * W_ + tx]);
        float s1 = __ldg(&sarb[(size_t)H_ * W_ + (size_t)h * W_ + tx]);
        size_t idx = (size_t)(h + 1) * WP + (tx + 1);
        xb[idx] = make_float4(s0, s1, fs0, fs1);
        __half2 ha = __floats2half2_rn(s0, s1);
        __half2 hh = __floats2half2_rn(fs0, fs1);
        hb[idx] = ((u64)(*(unsigned*)&hh) << 32) | (u64)(*(unsigned*)&ha);
    }
}

// ---------------------------------------------------------------------------
// Kernel D: build x-duplicated fp16 buffer: slot x = (px[x], px[min(x+1,WP-1)])
// ---------------------------------------------------------------------------
__global__ void kD_dup() {
    int i = blockIdx.x * blockDim.x + threadIdx.x;
    if (i >= B_ * HP * WP) return;
    int x = i % WP;
    u64 a = g_xh[i];
    u64 b = g_xh[i + (x < WP - 1 ? 1 : 0)];
    g_xh2[i] = make_ulonglong2(a, b);
}

// ---------------------------------------------------------------------------
// Kernel C: offset conv (row-pair weight amortization) + fp16 dup-gather
//           bilinear sampling + output dot.
// ---------------------------------------------------------------------------
__device__ __forceinline__ u64 sample_pt(const ulonglong2* __restrict__ xh2,
                                         float pyb, float pxb, float offy, float offx,
                                         u64 sd0, u64 sd1, u64 sd2, u64 sd3, u64 acc) {
    float py = pyb + offy, px = pxb + offx;
    float fy = floorf(py), fx = floorf(px);
    float y0f = fminf(fmaxf(fy,       0.f), (float)(HP - 1));
    float y1f = fminf(fmaxf(fy + 1.f, 0.f), (float)(HP - 1));
    float x0f = fminf(fmaxf(fx,       0.f), (float)(WP - 1));
    float x1f = fminf(fmaxf(fx + 1.f, 0.f), (float)(WP - 1));
    int y0 = (int)y0f, y1 = (int)y1f, x0 = (int)x0f, x1 = (int)x1f;

    float pyc = fminf(fmaxf(py, 0.f), (float)(HP - 1));
    float pxc = fminf(fmaxf(px, 0.f), (float)(WP - 1));
    float wy0 = 1.f + (y0f - pyc);
    float wy1 = 1.f - (y1f - pyc);
    float wx0 = 1.f + (x0f - pxc);
    float wx1 = 1.f - (x1f - pxc);
    float glt = wy0 * wx0, grb = wy1 * wx1, glb = wy0 * wx1, grt = wy1 * wx0;

    ulonglong2 U0 = __ldg(&xh2[y0 * WP + x0]);   // (px x0, px x0+1) @ row y0
    ulonglong2 U1 = __ldg(&xh2[y1 * WP + x0]);   // @ row y1
    bool sel = (x1 == x0 + 1);
    u64 p00 = U0.x, p01 = sel ? U0.y : U0.x;
    u64 p10 = U1.x, p11 = sel ? U1.y : U1.x;

    u64 c01 = ffma2(dup2(glt), cvlo(p00), 0ULL);
    c01 = ffma2(dup2(grb), cvlo(p11), c01);
    c01 = ffma2(dup2(glb), cvlo(p01), c01);
    c01 = ffma2(dup2(grt), cvlo(p10), c01);
    u64 c23 = ffma2(dup2(glt), cvhi(p00), 0ULL);
    c23 = ffma2(dup2(grb), cvhi(p11), c23);
    c23 = ffma2(dup2(glb), cvhi(p01), c23);
    c23 = ffma2(dup2(grt), cvhi(p10), c23);

    float2 v01 = un2(c01), v23 = un2(c23);
    acc = ffma2(dup2(v01.x), sd0, acc);
    acc = ffma2(dup2(v01.y), sd1, acc);
    acc = ffma2(dup2(v23.x), sd2, acc);
    acc = ffma2(dup2(v23.y), sd3, acc);
    return acc;
}

#define TILE_H 8
__global__ void __launch_bounds__(128, 3)
kC_deform(const float* __restrict__ wp,
          const float* __restrict__ bp,
          const float* __restrict__ wdc,
          float* __restrict__ out) {
    __shared__ __align__(16) float4 srow[TILE_H + 2][WP];
    __shared__ __align__(16) float  swq[648];   // [j][tap][c]
    __shared__ __align__(16) float  sdc[72];    // [n][c][(o0,o1)]
    __shared__ float  sbp[18];

    int w  = threadIdx.x;
    int h0 = blockIdx.x * TILE_H;
    int b  = blockIdx.y;

    const float4* base = g_xp4 + (size_t)b * HP * WP;
    const ulonglong2* xh2 = g_xh2 + (size_t)b * HP * WP;

    for (int i = threadIdx.x; i < (TILE_H + 2) * WP; i += 128) {
        int ry = i / WP, rx = i % WP;
        srow[ry][rx] = base[(size_t)(h0 + ry) * WP + rx];
    }
    for (int i = threadIdx.x; i < 648; i += 128) {
        int j = i / 36, rem = i % 36, tap = rem / 4, c = rem % 4;
        swq[i] = wp[j * 36 + c * 9 + tap];
    }
    if (threadIdx.x < 72) {
        int i = threadIdx.x;
        int n = i / 8, rc = i % 8, c = rc / 2, o = rc % 2;
        sdc[i] = wdc[o * 36 + c * 9 + n];
    }
    if (threadIdx.x < 18) sbp[threadIdx.x] = bp[threadIdx.x];
    __syncthreads();

    const float pxbase = (float)(w + 1);

#pragma unroll 1
    for (int rp = 0; rp < TILE_H / 2; rp++) {
        int r0 = rp * 2;
        // taps for row pair (r0, r0+1): 4 smem rows x 3 kx, as (c01,c23) f32x2 pairs
        ulonglong2 ip[4][3];
#pragma unroll
        for (int ry = 0; ry < 4; ry++)
#pragma unroll
            for (int kx = 0; kx < 3; kx++)
                ip[ry][kx] = *(const ulonglong2*)&srow[r0 + ry][w + kx];

        u64 accp0 = 0ULL, accp1 = 0ULL;
        float py0 = (float)(h0 + r0 + 1);
        float py1 = (float)(h0 + r0 + 2);

#pragma unroll
        for (int n = 0; n < 9; n++) {
            u64 ay0 = 0ULL, ay1 = 0ULL, ax0 = 0ULL, ax1 = 0ULL;
#pragma unroll
            for (int ky = 0; ky < 3; ky++) {
#pragma unroll
                for (int kx = 0; kx < 3; kx++) {
                    int tap = ky * 3 + kx;
                    ulonglong2 wy = *(const ulonglong2*)&swq[(n * 9 + tap) * 4];
                    ulonglong2 wx = *(const ulonglong2*)&swq[((9 + n) * 9 + tap) * 4];
                    ay0 = ffma2(ip[ky    ][kx].x, wy.x, ay0);
                    ay0 = ffma2(ip[ky    ][kx].y, wy.y, ay0);
                    ay1 = ffma2(ip[ky + 1][kx].x, wy.x, ay1);
                    ay1 = ffma2(ip[ky + 1][kx].y, wy.y, ay1);
                    ax0 = ffma2(ip[ky    ][kx].x, wx.x, ax0);
                    ax0 = ffma2(ip[ky    ][kx].y, wx.y, ax0);
                    ax1 = ffma2(ip[ky + 1][kx].x, wx.x, ax1);
                    ax1 = ffma2(ip[ky + 1][kx].y, wx.y, ax1);
                }
            }
            float2 t;
            t = un2(ay0); float offy0 = t.x + t.y + sbp[n];
            t = un2(ay1); float offy1 = t.x + t.y + sbp[n];
            t = un2(ax0); float offx0 = t.x + t.y + sbp[9 + n];
            t = un2(ax1); float offx1 = t.x + t.y + sbp[9 + n];

            float dy = (float)(n / 3 - 1);
            float dx = (float)(n % 3 - 1);
            const u64* sd = (const u64*)&sdc[n * 8];
            u64 sd0 = sd[0], sd1 = sd[1], sd2 = sd[2], sd3 = sd[3];

            accp0 = sample_pt(xh2, py0 + dy, pxbase + dx, offy0, offx0,
                              sd0, sd1, sd2, sd3, accp0);
            accp1 = sample_pt(xh2, py1 + dy, pxbase + dx, offy1, offx1,
                              sd0, sd1, sd2, sd3, accp1);
        }

        int h = h0 + r0;
        float2 o0 = un2(accp0);
        float2 o1 = un2(accp1);
        out[((size_t)(b * 2 + 0) * H_ + h) * W_ + w] = o0.x;
        out[((size_t)(b * 2 + 1) * H_ + h) * W_ + w] = o0.y;
        out[((size_t)(b * 2 + 0) * H_ + h + 1) * W_ + w] = o1.x;
        out[((size_t)(b * 2 + 1) * H_ + h + 1) * W_ + w] = o1.y;
    }
}

// ---------------------------------------------------------------------------
extern "C" void kernel_launch(void* const* d_in, const int* in_sizes, int n_in,
                              void* d_out, int out_size) {
    const float* rgb = (const float*)d_in[0];
    const float* sar = (const float*)d_in[1];
    const float* wfm = (const float*)d_in[2];
    const float* wfs = (const float*)d_in[3];
    const float* wp  = (const float*)d_in[4];
    const float* bp  = (const float*)d_in[5];
    const float* wdc = (const float*)d_in[6];
    float* out = (float*)d_out;

    cudaFuncSetAttribute(kB_mat_fs_pack,
                         cudaFuncAttributeMaxDynamicSharedMemorySize, 196608);

    kA_avg_fm<<<(B_ * 128 * 128 + 255) / 256, 256>>>(rgb, wfm);
    kZ_zero_border<<<(B_ * HP + 255) / 256, 256>>>();
    kB_mat_fs_pack<<<dim3(H_ / KB_ROWS, B_), dim3(128, 4), 196608>>>(rgb, sar, wfs);
    kD_dup<<<(B_ * HP * WP + 255) / 256, 256>>>();
    kC_deform<<<dim3(H_ / TILE_H, B_), 128>>>(wp, bp, wdc, out);
}